// round 1
// baseline (speedup 1.0000x reference)
#include <cuda_runtime.h>
#include <math.h>

#define BB 16
#define TMAX 4096
#define DM 1024
#define HH 16
#define DHD 64
#define HALF 32
#define CHUNK 128
#define NCHUNK (TMAX / CHUNK)   // 32

// ---------------- device scratch (no allocation allowed) ----------------
__device__ float2 g_tab[TMAX * HALF];              // 1 MB rope table (cos, sin)
__device__ float  g_pqkv[3 * 8 * BB * DM];         // qkv split-k partials
__device__ float  g_qrot[BB * DM];                 // rotated q
__device__ float  g_knr [BB * DM];                 // rotated new k
__device__ float  g_vnew[BB * DM];                 // new v
__device__ float  g_pm[BB * HH * NCHUNK];          // attention partial max
__device__ float  g_pl[BB * HH * NCHUNK];          // attention partial sum
__device__ float  g_po[BB * HH * NCHUNK * DHD];    // attention partial out
__device__ float  g_att[BB * DM];                  // attended values
__device__ float  g_pout[8 * BB * DM];             // out-proj split-k partials

// ---------------- rope table ----------------
__global__ void k_tab() {
    int idx = blockIdx.x * blockDim.x + threadIdx.x;   // 131072
    int t = idx >> 5, f = idx & 31;
    float invf = (float)pow(10000.0, -(double)f / 32.0);
    float ang = (float)t * invf;       // same fp32 product as reference
    float s, c;
    sincosf(ang, &s, &c);              // accurate version (large-arg safe)
    g_tab[idx] = make_float2(c, s);
}

// ---------------- QKV projection: split-k partials ----------------
// grid (ct=8, et=8, mat=3), block 128
__global__ void k_qkv(const float* __restrict__ x,
                      const float* __restrict__ Wq,
                      const float* __restrict__ Wk,
                      const float* __restrict__ Wv) {
    __shared__ float xs[BB][128];
    int mat = blockIdx.z, et = blockIdx.y, ct = blockIdx.x;
    const float* W = (mat == 0) ? Wq : ((mat == 1) ? Wk : Wv);
    int e0 = et * 128;
    for (int i = threadIdx.x; i < BB * 128; i += 128) {
        int b = i >> 7, e = i & 127;
        xs[b][e] = x[b * DM + e0 + e];
    }
    __syncthreads();
    int c = ct * 128 + threadIdx.x;
    float acc[BB];
#pragma unroll
    for (int b = 0; b < BB; b++) acc[b] = 0.f;
    for (int i = 0; i < 128; i++) {
        float w = W[(size_t)(e0 + i) * DM + c];
#pragma unroll
        for (int b = 0; b < BB; b++) acc[b] = fmaf(xs[b][i], w, acc[b]);
    }
    float* p = g_pqkv + (size_t)(mat * 8 + et) * BB * DM;
#pragma unroll
    for (int b = 0; b < BB; b++) p[b * DM + c] = acc[b];
}

// ---------------- finish QKV: sum partials + bias, rope q & new-k ----------------
// grid 96, block 256  -> 24576 threads, one per (mat, b, head, dim-pair)
__global__ void k_finish(const float* __restrict__ bq,
                         const float* __restrict__ bk,
                         const float* __restrict__ bv,
                         const int*   __restrict__ cip) {
    int idx = blockIdx.x * blockDim.x + threadIdx.x;
    int mat = idx / (BB * 512);
    int r = idx % (BB * 512);
    int b = r / 512;
    int p = r % 512;
    int h = p >> 5, dp = p & 31;
    int c1 = h * 64 + dp, c2 = c1 + 32;
    const float* bias = (mat == 0) ? bq : ((mat == 1) ? bk : bv);
    float v1 = bias[c1], v2 = bias[c2];
    const float* base = g_pqkv + (size_t)mat * 8 * BB * DM + b * DM;
#pragma unroll
    for (int et = 0; et < 8; et++) {
        v1 += base[(size_t)et * BB * DM + c1];
        v2 += base[(size_t)et * BB * DM + c2];
    }
    if (mat == 2) {
        g_vnew[b * DM + c1] = v1;
        g_vnew[b * DM + c2] = v2;
    } else {
        int ci = *cip;
        float2 cs = g_tab[ci * HALF + dp];
        float r1 = v1 * cs.x - v2 * cs.y;
        float r2 = v1 * cs.y + v2 * cs.x;
        float* dst = (mat == 0) ? g_qrot : g_knr;
        dst[b * DM + c1] = r1;
        dst[b * DM + c2] = r2;
    }
}

// ---------------- attention: split-T online softmax ----------------
// grid (NCHUNK=32, H=16), block 512 (warp = batch b, lane = dim pair)
__global__ void __launch_bounds__(512, 2)
k_attn(const float* __restrict__ K, const float* __restrict__ V,
       const int* __restrict__ cip) {
    __shared__ float4 tab_s[CHUNK * HALF / 2];   // 32 KB
    int ci = *cip;
    int ch = blockIdx.x, h = blockIdx.y;
    int j0 = ch * CHUNK;
    if (j0 > ci) return;
    const float4* tsrc = (const float4*)(g_tab + (size_t)j0 * HALF);
    for (int i = threadIdx.x; i < CHUNK * HALF / 2; i += 512) tab_s[i] = tsrc[i];
    __syncthreads();

    int b = threadIdx.x >> 5, lane = threadIdx.x & 31;
    int jend = min(j0 + CHUNK, ci + 1);
    const float* q = g_qrot + (b * HH + h) * DHD;
    float q1 = q[lane], q2 = q[lane + 32];
    const float2* tabs = (const float2*)tab_s;
    size_t base = ((size_t)b * TMAX + j0) * DM + h * DHD;
    const float* kp = K + base;
    const float* vp = V + base;

    float m = -INFINITY, l = 0.f, o1 = 0.f, o2 = 0.f;
    for (int j = j0; j < jend; j++, kp += DM, vp += DM) {
        float kr1, kr2, v1, v2;
        if (j == ci) {
            const float* kn = g_knr + (b * HH + h) * DHD;
            const float* vn = g_vnew + (b * HH + h) * DHD;
            kr1 = kn[lane]; kr2 = kn[lane + 32];
            v1 = vn[lane];  v2 = vn[lane + 32];
        } else {
            float k1 = kp[lane], k2 = kp[lane + 32];
            float2 cs = tabs[(j - j0) * HALF + lane];
            kr1 = k1 * cs.x - k2 * cs.y;
            kr2 = k1 * cs.y + k2 * cs.x;
            v1 = vp[lane];  v2 = vp[lane + 32];
        }
        float pdot = q1 * kr1 + q2 * kr2;
#pragma unroll
        for (int off = 16; off; off >>= 1)
            pdot += __shfl_xor_sync(0xffffffffu, pdot, off);
        float s = pdot * 0.125f;      // 1/sqrt(64)
        float mn = fmaxf(m, s);
        float corr = __expf(m - mn);
        float w = __expf(s - mn);
        l = l * corr + w;
        o1 = fmaf(o1, corr, w * v1);
        o2 = fmaf(o2, corr, w * v2);
        m = mn;
    }
    int pi = (b * HH + h) * NCHUNK + ch;
    if (lane == 0) { g_pm[pi] = m; g_pl[pi] = l; }
    g_po[(size_t)pi * DHD + lane] = o1;
    g_po[(size_t)pi * DHD + lane + 32] = o2;
}

// ---------------- combine split-T partials ----------------
// grid (16 h, 16 b), block 64
__global__ void k_reduce(const int* __restrict__ cip) {
    int ci = *cip;
    int nc = ci / CHUNK + 1;
    int h = blockIdx.x, b = blockIdx.y;
    int d = threadIdx.x;
    int base = (b * HH + h) * NCHUNK;
    float M = -INFINITY;
    for (int c = 0; c < nc; c++) M = fmaxf(M, g_pm[base + c]);
    float L = 0.f, O = 0.f;
    for (int c = 0; c < nc; c++) {
        float e = __expf(g_pm[base + c] - M);
        L += g_pl[base + c] * e;
        O += g_po[(size_t)(base + c) * DHD + d] * e;
    }
    g_att[b * DM + h * DHD + d] = O / L;
}

// ---------------- output projection: split-k partials ----------------
// grid (et=8, kt=8), block 128
__global__ void k_outp(const float* __restrict__ Wo) {
    __shared__ float as[BB][128];
    int kt = blockIdx.y, et = blockIdx.x;
    int k0 = kt * 128;
    for (int i = threadIdx.x; i < BB * 128; i += 128) {
        int b = i >> 7, kk = i & 127;
        as[b][kk] = g_att[b * DM + k0 + kk];
    }
    __syncthreads();
    int e = et * 128 + threadIdx.x;
    float acc[BB];
#pragma unroll
    for (int b = 0; b < BB; b++) acc[b] = 0.f;
    for (int i = 0; i < 128; i++) {
        float w = Wo[(size_t)(k0 + i) * DM + e];
#pragma unroll
        for (int b = 0; b < BB; b++) acc[b] = fmaf(as[b][i], w, acc[b]);
    }
#pragma unroll
    for (int b = 0; b < BB; b++) g_pout[(size_t)(kt * BB + b) * DM + e] = acc[b];
}

// ---------------- final sum + bias ----------------
// grid 64, block 256
__global__ void k_outf(const float* __restrict__ bo, float* __restrict__ out) {
    int idx = blockIdx.x * blockDim.x + threadIdx.x;   // 16384
    int b = idx >> 10, e = idx & 1023;
    float v = bo[e];
#pragma unroll
    for (int kt = 0; kt < 8; kt++) v += g_pout[(size_t)(kt * BB + b) * DM + e];
    out[idx] = v;
}

extern "C" void kernel_launch(void* const* d_in, const int* in_sizes, int n_in,
                              void* d_out, int out_size) {
    const float* x   = (const float*)d_in[0];
    const float* cK  = (const float*)d_in[1];
    const float* cV  = (const float*)d_in[2];
    const float* Wq  = (const float*)d_in[3];
    const float* bq  = (const float*)d_in[4];
    const float* Wk  = (const float*)d_in[5];
    const float* bk  = (const float*)d_in[6];
    const float* Wv  = (const float*)d_in[7];
    const float* bv  = (const float*)d_in[8];
    const float* Wo  = (const float*)d_in[9];
    const float* bo  = (const float*)d_in[10];
    const int*   cip = (const int*)d_in[11];
    float* out = (float*)d_out;

    k_tab<<<512, 256>>>();
    k_qkv<<<dim3(8, 8, 3), 128>>>(x, Wq, Wk, Wv);
    k_finish<<<96, 256>>>(bq, bk, bv, cip);
    k_attn<<<dim3(NCHUNK, HH), 512>>>(cK, cV, cip);
    k_reduce<<<dim3(HH, BB), 64>>>(cip);
    k_outp<<<dim3(8, 8), 128>>>(Wo);
    k_outf<<<64, 256>>>(bo, out);
}

// round 2
// speedup vs baseline: 1.0014x; 1.0014x over previous
#include <cuda_runtime.h>
#include <math.h>

#define BB 16
#define TMAX 4096
#define DM 1024
#define HH 16
#define DHD 64
#define HALF 32
#define CHUNK 128
#define NCHUNK (TMAX / CHUNK)   // 32

// ---------------- device scratch (no allocation allowed) ----------------
__device__ float2 g_tab[TMAX * HALF];              // 1 MB rope table (cos, sin)
__device__ float  g_pqkv[3 * 8 * BB * DM];         // qkv split-k partials
__device__ float  g_qrot[BB * DM];                 // rotated q
__device__ float  g_knr [BB * DM];                 // rotated new k
__device__ float  g_vnew[BB * DM];                 // new v
__device__ float  g_pm[BB * HH * NCHUNK];          // attention partial max
__device__ float  g_pl[BB * HH * NCHUNK];          // attention partial sum
__device__ float  g_po[BB * HH * NCHUNK * DHD];    // attention partial out
__device__ float  g_att[BB * DM];                  // attended values
__device__ float  g_pout[8 * BB * DM];             // out-proj split-k partials

// ---------------- rope table ----------------
__global__ void k_tab() {
    int idx = blockIdx.x * blockDim.x + threadIdx.x;   // 131072
    int t = idx >> 5, f = idx & 31;
    float invf = (float)pow(10000.0, -(double)f / 32.0);
    float ang = (float)t * invf;       // same fp32 product as reference
    float s, c;
    sincosf(ang, &s, &c);              // accurate version (large-arg safe)
    g_tab[idx] = make_float2(c, s);
}

// ---------------- QKV projection: split-k partials ----------------
// grid (ct=8, et=8, mat=3), block 128
__global__ void k_qkv(const float* __restrict__ x,
                      const float* __restrict__ Wq,
                      const float* __restrict__ Wk,
                      const float* __restrict__ Wv) {
    __shared__ float xs[BB][128];
    int mat = blockIdx.z, et = blockIdx.y, ct = blockIdx.x;
    const float* W = (mat == 0) ? Wq : ((mat == 1) ? Wk : Wv);
    int e0 = et * 128;
    for (int i = threadIdx.x; i < BB * 128; i += 128) {
        int b = i >> 7, e = i & 127;
        xs[b][e] = x[b * DM + e0 + e];
    }
    __syncthreads();
    int c = ct * 128 + threadIdx.x;
    float acc[BB];
#pragma unroll
    for (int b = 0; b < BB; b++) acc[b] = 0.f;
    for (int i = 0; i < 128; i++) {
        float w = W[(size_t)(e0 + i) * DM + c];
#pragma unroll
        for (int b = 0; b < BB; b++) acc[b] = fmaf(xs[b][i], w, acc[b]);
    }
    float* p = g_pqkv + (size_t)(mat * 8 + et) * BB * DM;
#pragma unroll
    for (int b = 0; b < BB; b++) p[b * DM + c] = acc[b];
}

// ---------------- finish QKV: sum partials + bias, rope q & new-k ----------------
// grid 96, block 256  -> 24576 threads, one per (mat, b, head, dim-pair)
__global__ void k_finish(const float* __restrict__ bq,
                         const float* __restrict__ bk,
                         const float* __restrict__ bv,
                         const int*   __restrict__ cip) {
    int idx = blockIdx.x * blockDim.x + threadIdx.x;
    int mat = idx / (BB * 512);
    int r = idx % (BB * 512);
    int b = r / 512;
    int p = r % 512;
    int h = p >> 5, dp = p & 31;
    int c1 = h * 64 + dp, c2 = c1 + 32;
    const float* bias = (mat == 0) ? bq : ((mat == 1) ? bk : bv);
    float v1 = bias[c1], v2 = bias[c2];
    const float* base = g_pqkv + (size_t)mat * 8 * BB * DM + b * DM;
#pragma unroll
    for (int et = 0; et < 8; et++) {
        v1 += base[(size_t)et * BB * DM + c1];
        v2 += base[(size_t)et * BB * DM + c2];
    }
    if (mat == 2) {
        g_vnew[b * DM + c1] = v1;
        g_vnew[b * DM + c2] = v2;
    } else {
        int ci = *cip;
        float2 cs = g_tab[ci * HALF + dp];
        float r1 = v1 * cs.x - v2 * cs.y;
        float r2 = v1 * cs.y + v2 * cs.x;
        float* dst = (mat == 0) ? g_qrot : g_knr;
        dst[b * DM + c1] = r1;
        dst[b * DM + c2] = r2;
    }
}

// ---------------- attention: split-T online softmax ----------------
// grid (NCHUNK=32, H=16), block 512 (warp = batch b, lane = dim pair)
__global__ void __launch_bounds__(512, 2)
k_attn(const float* __restrict__ K, const float* __restrict__ V,
       const int* __restrict__ cip) {
    __shared__ float4 tab_s[CHUNK * HALF / 2];   // 32 KB
    int ci = *cip;
    int ch = blockIdx.x, h = blockIdx.y;
    int j0 = ch * CHUNK;
    if (j0 > ci) return;
    const float4* tsrc = (const float4*)(g_tab + (size_t)j0 * HALF);
    for (int i = threadIdx.x; i < CHUNK * HALF / 2; i += 512) tab_s[i] = tsrc[i];
    __syncthreads();

    int b = threadIdx.x >> 5, lane = threadIdx.x & 31;
    int jend = min(j0 + CHUNK, ci + 1);
    const float* q = g_qrot + (b * HH + h) * DHD;
    float q1 = q[lane], q2 = q[lane + 32];
    const float2* tabs = (const float2*)tab_s;
    size_t base = ((size_t)b * TMAX + j0) * DM + h * DHD;
    const float* kp = K + base;
    const float* vp = V + base;

    float m = -INFINITY, l = 0.f, o1 = 0.f, o2 = 0.f;
    for (int j = j0; j < jend; j++, kp += DM, vp += DM) {
        float kr1, kr2, v1, v2;
        if (j == ci) {
            const float* kn = g_knr + (b * HH + h) * DHD;
            const float* vn = g_vnew + (b * HH + h) * DHD;
            kr1 = kn[lane]; kr2 = kn[lane + 32];
            v1 = vn[lane];  v2 = vn[lane + 32];
        } else {
            float k1 = kp[lane], k2 = kp[lane + 32];
            float2 cs = tabs[(j - j0) * HALF + lane];
            kr1 = k1 * cs.x - k2 * cs.y;
            kr2 = k1 * cs.y + k2 * cs.x;
            v1 = vp[lane];  v2 = vp[lane + 32];
        }
        float pdot = q1 * kr1 + q2 * kr2;
#pragma unroll
        for (int off = 16; off; off >>= 1)
            pdot += __shfl_xor_sync(0xffffffffu, pdot, off);
        float s = pdot * 0.125f;      // 1/sqrt(64)
        float mn = fmaxf(m, s);
        float corr = __expf(m - mn);
        float w = __expf(s - mn);
        l = l * corr + w;
        o1 = fmaf(o1, corr, w * v1);
        o2 = fmaf(o2, corr, w * v2);
        m = mn;
    }
    int pi = (b * HH + h) * NCHUNK + ch;
    if (lane == 0) { g_pm[pi] = m; g_pl[pi] = l; }
    g_po[(size_t)pi * DHD + lane] = o1;
    g_po[(size_t)pi * DHD + lane + 32] = o2;
}

// ---------------- combine split-T partials ----------------
// grid (16 h, 16 b), block 64
__global__ void k_reduce(const int* __restrict__ cip) {
    int ci = *cip;
    int nc = ci / CHUNK + 1;
    int h = blockIdx.x, b = blockIdx.y;
    int d = threadIdx.x;
    int base = (b * HH + h) * NCHUNK;
    float M = -INFINITY;
    for (int c = 0; c < nc; c++) M = fmaxf(M, g_pm[base + c]);
    float L = 0.f, O = 0.f;
    for (int c = 0; c < nc; c++) {
        float e = __expf(g_pm[base + c] - M);
        L += g_pl[base + c] * e;
        O += g_po[(size_t)(base + c) * DHD + d] * e;
    }
    g_att[b * DM + h * DHD + d] = O / L;
}

// ---------------- output projection: split-k partials ----------------
// grid (et=8, kt=8), block 128
__global__ void k_outp(const float* __restrict__ Wo) {
    __shared__ float as[BB][128];
    int kt = blockIdx.y, et = blockIdx.x;
    int k0 = kt * 128;
    for (int i = threadIdx.x; i < BB * 128; i += 128) {
        int b = i >> 7, kk = i & 127;
        as[b][kk] = g_att[b * DM + k0 + kk];
    }
    __syncthreads();
    int e = et * 128 + threadIdx.x;
    float acc[BB];
#pragma unroll
    for (int b = 0; b < BB; b++) acc[b] = 0.f;
    for (int i = 0; i < 128; i++) {
        float w = Wo[(size_t)(k0 + i) * DM + e];
#pragma unroll
        for (int b = 0; b < BB; b++) acc[b] = fmaf(as[b][i], w, acc[b]);
    }
#pragma unroll
    for (int b = 0; b < BB; b++) g_pout[(size_t)(kt * BB + b) * DM + e] = acc[b];
}

// ---------------- final sum + bias ----------------
// grid 64, block 256
__global__ void k_outf(const float* __restrict__ bo, float* __restrict__ out) {
    int idx = blockIdx.x * blockDim.x + threadIdx.x;   // 16384
    int b = idx >> 10, e = idx & 1023;
    float v = bo[e];
#pragma unroll
    for (int kt = 0; kt < 8; kt++) v += g_pout[(size_t)(kt * BB + b) * DM + e];
    out[idx] = v;
}

extern "C" void kernel_launch(void* const* d_in, const int* in_sizes, int n_in,
                              void* d_out, int out_size) {
    const float* x   = (const float*)d_in[0];
    const float* cK  = (const float*)d_in[1];
    const float* cV  = (const float*)d_in[2];
    const float* Wq  = (const float*)d_in[3];
    const float* bq  = (const float*)d_in[4];
    const float* Wk  = (const float*)d_in[5];
    const float* bk  = (const float*)d_in[6];
    const float* Wv  = (const float*)d_in[7];
    const float* bv  = (const float*)d_in[8];
    const float* Wo  = (const float*)d_in[9];
    const float* bo  = (const float*)d_in[10];
    const int*   cip = (const int*)d_in[11];
    float* out = (float*)d_out;

    k_tab<<<512, 256>>>();
    k_qkv<<<dim3(8, 8, 3), 128>>>(x, Wq, Wk, Wv);
    k_finish<<<96, 256>>>(bq, bk, bv, cip);
    k_attn<<<dim3(NCHUNK, HH), 512>>>(cK, cV, cip);
    k_reduce<<<dim3(HH, BB), 64>>>(cip);
    k_outp<<<dim3(8, 8), 128>>>(Wo);
    k_outf<<<64, 256>>>(bo, out);
}

// round 3
// speedup vs baseline: 1.9934x; 1.9907x over previous
#include <cuda_runtime.h>
#include <math.h>

#define BB 16
#define TMAX 4096
#define DM 1024
#define HH 16
#define DHD 64
#define HALF 32
#define NCHUNK 32          // strided position chunks

// ---------------- device scratch ----------------
__device__ float2 g_tab[TMAX * HALF];                 // 1 MB rope table (cos, sin)
__device__ float  g_pqkv[3 * 16 * BB * DM];           // qkv split-k partials (16 kt)
__device__ float  g_qrot[BB * DM];                    // rotated q
__device__ float  g_knr [BB * DM];                    // rotated new k
__device__ float  g_vnew[BB * DM];                    // new v
__device__ float  g_pm[BB * HH * NCHUNK];             // attention partial max
__device__ float  g_pl[BB * HH * NCHUNK];             // attention partial sum
__device__ float  g_po[BB * HH * NCHUNK * DHD];       // attention partial out
__device__ float  g_att[BB * DM];                     // attended values
__device__ float  g_pout[16 * BB * DM];               // out-proj split-k partials

// ---------------- fused: rope table (z==3) + QKV split-k (z<3) ----------------
// grid (8, 16, 4), block 128
__global__ void k_qkv(const float* __restrict__ x,
                      const float* __restrict__ Wq,
                      const float* __restrict__ Wk,
                      const float* __restrict__ Wv) {
    if (blockIdx.z == 3) {
        // rope table: 131072 entries, 16384 threads x 8
        int gid = (blockIdx.y * 8 + blockIdx.x) * 128 + threadIdx.x;
        int f = gid & 31;
        float invf = exp2f((float)f * -0.41524101186092029f);  // -log2(10000)/32
#pragma unroll
        for (int r = 0; r < 8; r++) {
            int idx = r * 16384 + gid;
            int t = idx >> 5;
            float s, c;
            sincosf((float)t * invf, &s, &c);
            g_tab[idx] = make_float2(c, s);
        }
        return;
    }
    __shared__ float xs[BB][64];
    int mat = blockIdx.z, kt = blockIdx.y, ct = blockIdx.x;
    const float* W = (mat == 0) ? Wq : ((mat == 1) ? Wk : Wv);
    int k0 = kt * 64;
    for (int i = threadIdx.x; i < BB * 64; i += 128) {
        int b = i >> 6, e = i & 63;
        xs[b][e] = x[b * DM + k0 + e];
    }
    __syncthreads();
    int c = ct * 128 + threadIdx.x;
    float acc[BB];
#pragma unroll
    for (int b = 0; b < BB; b++) acc[b] = 0.f;
#pragma unroll 8
    for (int i = 0; i < 64; i++) {
        float w = W[(size_t)(k0 + i) * DM + c];
#pragma unroll
        for (int b = 0; b < BB; b++) acc[b] = fmaf(xs[b][i], w, acc[b]);
    }
    float* p = g_pqkv + (size_t)(mat * 16 + kt) * BB * DM;
#pragma unroll
    for (int b = 0; b < BB; b++) p[b * DM + c] = acc[b];
}

// ---------------- finish QKV: sum 16 partials + bias, rope q & new-k ----------------
// grid 96, block 256  -> 24576 threads, one per (mat, b, head, dim-pair)
__global__ void k_finish(const float* __restrict__ bq,
                         const float* __restrict__ bk,
                         const float* __restrict__ bv,
                         const int*   __restrict__ cip) {
    int idx = blockIdx.x * blockDim.x + threadIdx.x;
    int mat = idx / (BB * 512);
    int r = idx % (BB * 512);
    int b = r / 512;
    int p = r % 512;
    int h = p >> 5, dp = p & 31;
    int c1 = h * 64 + dp, c2 = c1 + 32;
    const float* bias = (mat == 0) ? bq : ((mat == 1) ? bk : bv);
    float v1 = bias[c1], v2 = bias[c2];
    const float* base = g_pqkv + (size_t)mat * 16 * BB * DM + b * DM;
#pragma unroll
    for (int kt = 0; kt < 16; kt++) {
        v1 += base[(size_t)kt * BB * DM + c1];
        v2 += base[(size_t)kt * BB * DM + c2];
    }
    if (mat == 2) {
        g_vnew[b * DM + c1] = v1;
        g_vnew[b * DM + c2] = v2;
    } else {
        int ci = *cip;
        float2 cs = g_tab[ci * HALF + dp];
        float r1 = v1 * cs.x - v2 * cs.y;
        float r2 = v1 * cs.y + v2 * cs.x;
        float* dst = (mat == 0) ? g_qrot : g_knr;
        dst[b * DM + c1] = r1;
        dst[b * DM + c2] = r2;
    }
}

// ---------------- attention: strided split-T online softmax ----------------
// grid (32, 16, 2), block 256 (warp = batch; z picks batch half; lane = dim pair)
__global__ void __launch_bounds__(256)
k_attn(const float* __restrict__ K, const float* __restrict__ V,
       const int* __restrict__ cip) {
    int ci = *cip;
    int ch = blockIdx.x, h = blockIdx.y;
    int b = blockIdx.z * 8 + (threadIdx.x >> 5);
    int lane = threadIdx.x & 31;

    const float* q = g_qrot + (b * HH + h) * DHD;
    float q1 = q[lane], q2 = q[lane + 32];
    size_t rowstep = (size_t)DM;
    const float* kbase = K + ((size_t)b * TMAX) * DM + h * DHD;
    const float* vbase = V + ((size_t)b * TMAX) * DM + h * DHD;

    float m = -INFINITY, l = 0.f, o1 = 0.f, o2 = 0.f;

    int j = ch;
    // pairs (j, j+32), both < ci
    for (; j + 32 < ci; j += 64) {
        const float* kp0 = kbase + (size_t)j * rowstep;
        const float* kp1 = kp0 + 32 * rowstep;
        const float* vp0 = vbase + (size_t)j * rowstep;
        const float* vp1 = vp0 + 32 * rowstep;
        float ka1 = __ldcs(kp0 + lane), ka2 = __ldcs(kp0 + lane + 32);
        float kb1 = __ldcs(kp1 + lane), kb2 = __ldcs(kp1 + lane + 32);
        float va1 = __ldcs(vp0 + lane), va2 = __ldcs(vp0 + lane + 32);
        float vb1 = __ldcs(vp1 + lane), vb2 = __ldcs(vp1 + lane + 32);
        float2 csa = g_tab[(size_t)j * HALF + lane];
        float2 csb = g_tab[(size_t)(j + 32) * HALF + lane];
        float da = (ka1 * csa.x - ka2 * csa.y) * q1 + (ka1 * csa.y + ka2 * csa.x) * q2;
        float db = (kb1 * csb.x - kb2 * csb.y) * q1 + (kb1 * csb.y + kb2 * csb.x) * q2;
#pragma unroll
        for (int off = 16; off; off >>= 1) {
            da += __shfl_xor_sync(0xffffffffu, da, off);
            db += __shfl_xor_sync(0xffffffffu, db, off);
        }
        float s0 = da * 0.125f, s1 = db * 0.125f;
        float mn = fmaxf(m, fmaxf(s0, s1));
        float corr = __expf(m - mn);
        float e0 = __expf(s0 - mn);
        float e1 = __expf(s1 - mn);
        l = l * corr + e0 + e1;
        o1 = fmaf(o1, corr, e0 * va1 + e1 * vb1);
        o2 = fmaf(o2, corr, e0 * va2 + e1 * vb2);
        m = mn;
    }
    // at most one leftover regular position
    if (j < ci) {
        const float* kp0 = kbase + (size_t)j * rowstep;
        const float* vp0 = vbase + (size_t)j * rowstep;
        float k1 = __ldcs(kp0 + lane), k2 = __ldcs(kp0 + lane + 32);
        float v1 = __ldcs(vp0 + lane), v2 = __ldcs(vp0 + lane + 32);
        float2 cs = g_tab[(size_t)j * HALF + lane];
        float d = (k1 * cs.x - k2 * cs.y) * q1 + (k1 * cs.y + k2 * cs.x) * q2;
#pragma unroll
        for (int off = 16; off; off >>= 1) d += __shfl_xor_sync(0xffffffffu, d, off);
        float s = d * 0.125f;
        float mn = fmaxf(m, s);
        float corr = __expf(m - mn);
        float e = __expf(s - mn);
        l = l * corr + e;
        o1 = fmaf(o1, corr, e * v1);
        o2 = fmaf(o2, corr, e * v2);
        m = mn;
    }
    // position ci (new k/v) handled by its owner chunk
    if ((ci & 31) == ch) {
        const float* kn = g_knr + (b * HH + h) * DHD;
        const float* vn = g_vnew + (b * HH + h) * DHD;
        float k1 = kn[lane], k2 = kn[lane + 32];
        float v1 = vn[lane], v2 = vn[lane + 32];
        float d = k1 * q1 + k2 * q2;
#pragma unroll
        for (int off = 16; off; off >>= 1) d += __shfl_xor_sync(0xffffffffu, d, off);
        float s = d * 0.125f;
        float mn = fmaxf(m, s);
        float corr = __expf(m - mn);
        float e = __expf(s - mn);
        l = l * corr + e;
        o1 = fmaf(o1, corr, e * v1);
        o2 = fmaf(o2, corr, e * v2);
        m = mn;
    }

    int pi = (b * HH + h) * NCHUNK + ch;
    if (lane == 0) { g_pm[pi] = m; g_pl[pi] = l; }
    g_po[(size_t)pi * DHD + lane] = o1;
    g_po[(size_t)pi * DHD + lane + 32] = o2;
}

// ---------------- combine split-T partials ----------------
// grid (16 h, 16 b), block 64  (empty chunks have m=-inf, l=0 -> contribute 0)
__global__ void k_reduce() {
    int h = blockIdx.x, b = blockIdx.y;
    int d = threadIdx.x;
    int base = (b * HH + h) * NCHUNK;
    float M = -INFINITY;
#pragma unroll
    for (int c = 0; c < NCHUNK; c++) M = fmaxf(M, g_pm[base + c]);
    float L = 0.f, O = 0.f;
#pragma unroll
    for (int c = 0; c < NCHUNK; c++) {
        float e = __expf(g_pm[base + c] - M);
        L += g_pl[base + c] * e;
        O += g_po[(size_t)(base + c) * DHD + d] * e;
    }
    g_att[b * DM + h * DHD + d] = O / L;
}

// ---------------- output projection: split-k partials ----------------
// grid (et=8, kt=16), block 128
__global__ void k_outp(const float* __restrict__ Wo) {
    __shared__ float as[BB][64];
    int kt = blockIdx.y, et = blockIdx.x;
    int k0 = kt * 64;
    for (int i = threadIdx.x; i < BB * 64; i += 128) {
        int b = i >> 6, kk = i & 63;
        as[b][kk] = g_att[b * DM + k0 + kk];
    }
    __syncthreads();
    int e = et * 128 + threadIdx.x;
    float acc[BB];
#pragma unroll
    for (int b = 0; b < BB; b++) acc[b] = 0.f;
#pragma unroll 8
    for (int i = 0; i < 64; i++) {
        float w = Wo[(size_t)(k0 + i) * DM + e];
#pragma unroll
        for (int b = 0; b < BB; b++) acc[b] = fmaf(as[b][i], w, acc[b]);
    }
#pragma unroll
    for (int b = 0; b < BB; b++) g_pout[(size_t)(kt * BB + b) * DM + e] = acc[b];
}

// ---------------- final sum + bias ----------------
// grid 64, block 256
__global__ void k_outf(const float* __restrict__ bo, float* __restrict__ out) {
    int idx = blockIdx.x * blockDim.x + threadIdx.x;   // 16384
    int b = idx >> 10, e = idx & 1023;
    float v = bo[e];
#pragma unroll
    for (int kt = 0; kt < 16; kt++) v += g_pout[(size_t)(kt * BB + b) * DM + e];
    out[idx] = v;
}

extern "C" void kernel_launch(void* const* d_in, const int* in_sizes, int n_in,
                              void* d_out, int out_size) {
    const float* x   = (const float*)d_in[0];
    const float* cK  = (const float*)d_in[1];
    const float* cV  = (const float*)d_in[2];
    const float* Wq  = (const float*)d_in[3];
    const float* bq  = (const float*)d_in[4];
    const float* Wk  = (const float*)d_in[5];
    const float* bk  = (const float*)d_in[6];
    const float* Wv  = (const float*)d_in[7];
    const float* bv  = (const float*)d_in[8];
    const float* Wo  = (const float*)d_in[9];
    const float* bo  = (const float*)d_in[10];
    const int*   cip = (const int*)d_in[11];
    float* out = (float*)d_out;

    k_qkv<<<dim3(8, 16, 4), 128>>>(x, Wq, Wk, Wv);   // z==3 slice builds rope table
    k_finish<<<96, 256>>>(bq, bk, bv, cip);
    k_attn<<<dim3(NCHUNK, HH, 2), 256>>>(cK, cV, cip);
    k_reduce<<<dim3(HH, BB), 64>>>();
    k_outp<<<dim3(8, 16), 128>>>(Wo);
    k_outf<<<64, 256>>>(bo, out);
}

// round 4
// speedup vs baseline: 2.3999x; 1.2039x over previous
#include <cuda_runtime.h>
#include <math.h>

#define BB 16
#define TMAX 4096
#define DM 1024
#define HH 16
#define DHD 64
#define HALF 32
#define NCHUNK 32          // strided position chunks

// ---------------- device scratch ----------------
__device__ float2 g_tab[TMAX * HALF];                 // 1 MB rope table (cos, sin)
__device__ float  g_pqkv[3 * 16 * BB * DM];           // qkv split-k partials (16 kt)
__device__ float  g_qrot[BB * DM];                    // rotated q (pre-scaled by 1/8)
__device__ float  g_knr [BB * DM];                    // rotated new k
__device__ float  g_vnew[BB * DM];                    // new v
__device__ float  g_pm[BB * HH * NCHUNK];             // attention partial max
__device__ float  g_pl[BB * HH * NCHUNK];             // attention partial sum
__device__ float  g_po[BB * HH * NCHUNK * DHD];       // attention partial out
__device__ float  g_att[BB * DM];                     // attended values
__device__ float  g_pout[16 * BB * DM];               // out-proj split-k partials

// ---------------- fused: rope table (z==3) + QKV split-k (z<3) ----------------
// grid (8, 16, 4), block 128
__global__ void k_qkv(const float* __restrict__ x,
                      const float* __restrict__ Wq,
                      const float* __restrict__ Wk,
                      const float* __restrict__ Wv) {
    if (blockIdx.z == 3) {
        int gid = (blockIdx.y * 8 + blockIdx.x) * 128 + threadIdx.x;
        int f = gid & 31;
        float invf = exp2f((float)f * -0.41524101186092029f);  // -log2(10000)/32
#pragma unroll
        for (int r = 0; r < 8; r++) {
            int idx = r * 16384 + gid;
            int t = idx >> 5;
            float s, c;
            sincosf((float)t * invf, &s, &c);
            g_tab[idx] = make_float2(c, s);
        }
        return;
    }
    __shared__ float xs[BB][64];
    int mat = blockIdx.z, kt = blockIdx.y, ct = blockIdx.x;
    const float* W = (mat == 0) ? Wq : ((mat == 1) ? Wk : Wv);
    int k0 = kt * 64;
    for (int i = threadIdx.x; i < BB * 64; i += 128) {
        int b = i >> 6, e = i & 63;
        xs[b][e] = x[b * DM + k0 + e];
    }
    __syncthreads();
    int c = ct * 128 + threadIdx.x;
    float acc[BB];
#pragma unroll
    for (int b = 0; b < BB; b++) acc[b] = 0.f;
#pragma unroll 8
    for (int i = 0; i < 64; i++) {
        float w = W[(size_t)(k0 + i) * DM + c];
#pragma unroll
        for (int b = 0; b < BB; b++) acc[b] = fmaf(xs[b][i], w, acc[b]);
    }
    float* p = g_pqkv + (size_t)(mat * 16 + kt) * BB * DM;
#pragma unroll
    for (int b = 0; b < BB; b++) p[b * DM + c] = acc[b];
}

// ---------------- finish QKV: sum 16 partials + bias, rope q & new-k ----------------
// grid 96, block 256
__global__ void k_finish(const float* __restrict__ bq,
                         const float* __restrict__ bk,
                         const float* __restrict__ bv,
                         const int*   __restrict__ cip) {
    int idx = blockIdx.x * blockDim.x + threadIdx.x;
    int mat = idx / (BB * 512);
    int r = idx % (BB * 512);
    int b = r / 512;
    int p = r % 512;
    int h = p >> 5, dp = p & 31;
    int c1 = h * 64 + dp, c2 = c1 + 32;
    const float* bias = (mat == 0) ? bq : ((mat == 1) ? bk : bv);
    float v1 = bias[c1], v2 = bias[c2];
    const float* base = g_pqkv + (size_t)mat * 16 * BB * DM + b * DM;
#pragma unroll
    for (int kt = 0; kt < 16; kt++) {
        v1 += base[(size_t)kt * BB * DM + c1];
        v2 += base[(size_t)kt * BB * DM + c2];
    }
    if (mat == 2) {
        g_vnew[b * DM + c1] = v1;
        g_vnew[b * DM + c2] = v2;
    } else {
        int ci = *cip;
        float2 cs = g_tab[ci * HALF + dp];
        float r1 = v1 * cs.x - v2 * cs.y;
        float r2 = v1 * cs.y + v2 * cs.x;
        if (mat == 0) {                 // fold 1/sqrt(64) into q
            g_qrot[b * DM + c1] = r1 * 0.125f;
            g_qrot[b * DM + c2] = r2 * 0.125f;
        } else {
            g_knr[b * DM + c1] = r1;
            g_knr[b * DM + c2] = r2;
        }
    }
}

// ---------------- attention: strided split-T online softmax, 4x unrolled ----------------
// grid (32, 16, 2), block 256 (warp = batch; z picks batch half; lane = dim pair)
__global__ void __launch_bounds__(256)
k_attn(const float* __restrict__ K, const float* __restrict__ V,
       const int* __restrict__ cip) {
    int ci = *cip;
    int ch = blockIdx.x, h = blockIdx.y;
    int b = blockIdx.z * 8 + (threadIdx.x >> 5);
    int lane = threadIdx.x & 31;

    const float* q = g_qrot + (b * HH + h) * DHD;
    float q1 = q[lane], q2 = q[lane + 32];
    const float* kbase = K + ((size_t)b * TMAX) * DM + h * DHD;
    const float* vbase = V + ((size_t)b * TMAX) * DM + h * DHD;

    float m = -INFINITY, l = 0.f, o1 = 0.f, o2 = 0.f;

    int j = ch;
    // 4 positions per iteration: j, j+32, j+64, j+96  (all < ci)
    for (; j + 96 < ci; j += 128) {
        const float* kp = kbase + (size_t)j * DM;
        const float* vp = vbase + (size_t)j * DM;
        float ka1 = __ldcs(kp + lane),             ka2 = __ldcs(kp + lane + 32);
        float kb1 = __ldcs(kp + 32 * DM + lane),   kb2 = __ldcs(kp + 32 * DM + lane + 32);
        float kc1 = __ldcs(kp + 64 * DM + lane),   kc2 = __ldcs(kp + 64 * DM + lane + 32);
        float kd1 = __ldcs(kp + 96 * DM + lane),   kd2 = __ldcs(kp + 96 * DM + lane + 32);
        float va1 = __ldcs(vp + lane),             va2 = __ldcs(vp + lane + 32);
        float vb1 = __ldcs(vp + 32 * DM + lane),   vb2 = __ldcs(vp + 32 * DM + lane + 32);
        float vc1 = __ldcs(vp + 64 * DM + lane),   vc2 = __ldcs(vp + 64 * DM + lane + 32);
        float vd1 = __ldcs(vp + 96 * DM + lane),   vd2 = __ldcs(vp + 96 * DM + lane + 32);
        float2 csa = g_tab[(size_t)j * HALF + lane];
        float2 csb = g_tab[(size_t)(j + 32) * HALF + lane];
        float2 csc = g_tab[(size_t)(j + 64) * HALF + lane];
        float2 csd = g_tab[(size_t)(j + 96) * HALF + lane];
        float da = (ka1 * csa.x - ka2 * csa.y) * q1 + (ka1 * csa.y + ka2 * csa.x) * q2;
        float db = (kb1 * csb.x - kb2 * csb.y) * q1 + (kb1 * csb.y + kb2 * csb.x) * q2;
        float dc = (kc1 * csc.x - kc2 * csc.y) * q1 + (kc1 * csc.y + kc2 * csc.x) * q2;
        float dd = (kd1 * csd.x - kd2 * csd.y) * q1 + (kd1 * csd.y + kd2 * csd.x) * q2;
#pragma unroll
        for (int off = 16; off; off >>= 1) {
            da += __shfl_xor_sync(0xffffffffu, da, off);
            db += __shfl_xor_sync(0xffffffffu, db, off);
            dc += __shfl_xor_sync(0xffffffffu, dc, off);
            dd += __shfl_xor_sync(0xffffffffu, dd, off);
        }
        float mx = fmaxf(fmaxf(da, db), fmaxf(dc, dd));
        float mn = fmaxf(m, mx);
        float corr = __expf(m - mn);
        float e0 = __expf(da - mn);
        float e1 = __expf(db - mn);
        float e2 = __expf(dc - mn);
        float e3 = __expf(dd - mn);
        l = l * corr + (e0 + e1) + (e2 + e3);
        o1 = fmaf(o1, corr, (e0 * va1 + e1 * vb1) + (e2 * vc1 + e3 * vd1));
        o2 = fmaf(o2, corr, (e0 * va2 + e1 * vb2) + (e2 * vc2 + e3 * vd2));
        m = mn;
    }
    // leftovers (up to 3 positions)
    for (; j < ci; j += 32) {
        const float* kp = kbase + (size_t)j * DM;
        const float* vp = vbase + (size_t)j * DM;
        float k1 = __ldcs(kp + lane), k2 = __ldcs(kp + lane + 32);
        float v1 = __ldcs(vp + lane), v2 = __ldcs(vp + lane + 32);
        float2 cs = g_tab[(size_t)j * HALF + lane];
        float d = (k1 * cs.x - k2 * cs.y) * q1 + (k1 * cs.y + k2 * cs.x) * q2;
#pragma unroll
        for (int off = 16; off; off >>= 1) d += __shfl_xor_sync(0xffffffffu, d, off);
        float mn = fmaxf(m, d);
        float corr = __expf(m - mn);
        float e = __expf(d - mn);
        l = l * corr + e;
        o1 = fmaf(o1, corr, e * v1);
        o2 = fmaf(o2, corr, e * v2);
        m = mn;
    }
    // position ci (new k/v), handled by its owner chunk
    if ((ci & 31) == ch) {
        const float* kn = g_knr + (b * HH + h) * DHD;
        const float* vn = g_vnew + (b * HH + h) * DHD;
        float k1 = kn[lane], k2 = kn[lane + 32];
        float v1 = vn[lane], v2 = vn[lane + 32];
        float d = k1 * q1 + k2 * q2;
#pragma unroll
        for (int off = 16; off; off >>= 1) d += __shfl_xor_sync(0xffffffffu, d, off);
        float mn = fmaxf(m, d);
        float corr = __expf(m - mn);
        float e = __expf(d - mn);
        l = l * corr + e;
        o1 = fmaf(o1, corr, e * v1);
        o2 = fmaf(o2, corr, e * v2);
        m = mn;
    }

    int pi = (b * HH + h) * NCHUNK + ch;
    if (lane == 0) { g_pm[pi] = m; g_pl[pi] = l; }
    g_po[(size_t)pi * DHD + lane] = o1;
    g_po[(size_t)pi * DHD + lane + 32] = o2;
}

// ---------------- combine split-T partials (parallel over 8 chunk-slices) ----------------
// grid (HH, BB) = 256 blocks, block 512: threadIdx = s*64 + d, slice s owns 4 chunks
__global__ void __launch_bounds__(512) k_reduce() {
    __shared__ float sO[8][DHD];
    __shared__ float sL[8];
    __shared__ float sM[8];
    int h = blockIdx.x, b = blockIdx.y;
    int d = threadIdx.x & 63, s = threadIdx.x >> 6;
    int base = (b * HH + h) * NCHUNK + s * 4;
    float m0 = g_pm[base + 0], m1 = g_pm[base + 1];
    float m2 = g_pm[base + 2], m3 = g_pm[base + 3];
    float M = fmaxf(fmaxf(m0, m1), fmaxf(m2, m3));
    if (d == 0) sM[s] = M;
    __syncthreads();
    float Mg = sM[0];
#pragma unroll
    for (int i = 1; i < 8; i++) Mg = fmaxf(Mg, sM[i]);
    float e0 = __expf(m0 - Mg), e1 = __expf(m1 - Mg);
    float e2 = __expf(m2 - Mg), e3 = __expf(m3 - Mg);
    const float* po = g_po + (size_t)base * DHD + d;
    float O = po[0] * e0 + po[DHD] * e1 + po[2 * DHD] * e2 + po[3 * DHD] * e3;
    sO[s][d] = O;
    if (d == 0)
        sL[s] = g_pl[base + 0] * e0 + g_pl[base + 1] * e1
              + g_pl[base + 2] * e2 + g_pl[base + 3] * e3;
    __syncthreads();
    if (s == 0) {
        float Ot = 0.f, Lt = 0.f;
#pragma unroll
        for (int i = 0; i < 8; i++) Ot += sO[i][d];
#pragma unroll
        for (int i = 0; i < 8; i++) Lt += sL[i];
        g_att[b * DM + h * DHD + d] = Ot / Lt;
    }
}

// ---------------- output projection: split-k partials ----------------
// grid (et=8, kt=16), block 128
__global__ void k_outp(const float* __restrict__ Wo) {
    __shared__ float as[BB][64];
    int kt = blockIdx.y, et = blockIdx.x;
    int k0 = kt * 64;
    for (int i = threadIdx.x; i < BB * 64; i += 128) {
        int b = i >> 6, kk = i & 63;
        as[b][kk] = g_att[b * DM + k0 + kk];
    }
    __syncthreads();
    int e = et * 128 + threadIdx.x;
    float acc[BB];
#pragma unroll
    for (int b = 0; b < BB; b++) acc[b] = 0.f;
#pragma unroll 8
    for (int i = 0; i < 64; i++) {
        float w = Wo[(size_t)(k0 + i) * DM + e];
#pragma unroll
        for (int b = 0; b < BB; b++) acc[b] = fmaf(as[b][i], w, acc[b]);
    }
#pragma unroll
    for (int b = 0; b < BB; b++) g_pout[(size_t)(kt * BB + b) * DM + e] = acc[b];
}

// ---------------- final sum + bias ----------------
// grid 64, block 256
__global__ void k_outf(const float* __restrict__ bo, float* __restrict__ out) {
    int idx = blockIdx.x * blockDim.x + threadIdx.x;   // 16384
    int b = idx >> 10, e = idx & 1023;
    float v = bo[e];
#pragma unroll
    for (int kt = 0; kt < 16; kt++) v += g_pout[(size_t)(kt * BB + b) * DM + e];
    out[idx] = v;
}

extern "C" void kernel_launch(void* const* d_in, const int* in_sizes, int n_in,
                              void* d_out, int out_size) {
    const float* x   = (const float*)d_in[0];
    const float* cK  = (const float*)d_in[1];
    const float* cV  = (const float*)d_in[2];
    const float* Wq  = (const float*)d_in[3];
    const float* bq  = (const float*)d_in[4];
    const float* Wk  = (const float*)d_in[5];
    const float* bk  = (const float*)d_in[6];
    const float* Wv  = (const float*)d_in[7];
    const float* bv  = (const float*)d_in[8];
    const float* Wo  = (const float*)d_in[9];
    const float* bo  = (const float*)d_in[10];
    const int*   cip = (const int*)d_in[11];
    float* out = (float*)d_out;

    k_qkv<<<dim3(8, 16, 4), 128>>>(x, Wq, Wk, Wv);   // z==3 slice builds rope table
    k_finish<<<96, 256>>>(bq, bk, bv, cip);
    k_attn<<<dim3(NCHUNK, HH, 2), 256>>>(cK, cV, cip);
    k_reduce<<<dim3(HH, BB), 512>>>();
    k_outp<<<dim3(8, 16), 128>>>(Wo);
    k_outf<<<64, 256>>>(bo, out);
}